// round 8
// baseline (speedup 1.0000x reference)
#include <cuda_runtime.h>
#include <math.h>

#define N_NODES 50000
#define N_EDGES 800000
#define D 128
#define SCAN_B 1024
#define N_SBLK ((N_NODES + SCAN_B - 1) / SCAN_B)   // 49

// ---------------- scratch (device globals; self-restoring across replays) --
__device__ float g_xT [(size_t)N_NODES * D];   // X transposed (written by gemm1)
__device__ float g_xw [(size_t)N_NODES * D];   // GEMM out (L1 raw, L2 pre-scaled)
__device__ float g_f1 [(size_t)N_NODES * D];   // layer-1 output
__device__ float g_y  [(size_t)N_NODES * D];   // layer-2 output (+residual)
__device__ float g_deg[N_NODES];               // dinv = rsqrt(1 + in_deg)
__device__ int   g_hist[N_NODES];              // in-degree (zeroed by k_final)
__device__ int   g_rowstart[N_NODES];          // CSR row starts (by dst)
__device__ int   g_cursor[N_NODES];            // fill cursors
__device__ int   g_csrc[N_EDGES];              // CSR src indices
__device__ int   g_bsum[64];                   // scan block sums
__device__ float g_cs [D];                     // col sum of y  (zeroed by gemm L1)
__device__ float g_cs2[D];                     // col sum of y^2

__device__ __forceinline__ float gelu_exact(float v) {
    return v * normcdff(v);     // jax.nn.gelu(approximate=False)
}

__device__ __forceinline__ void fma2(unsigned long long& acc,
                                     unsigned long long a,
                                     unsigned long long b) {
    asm("fma.rn.f32x2 %0, %1, %2, %0;" : "+l"(acc) : "l"(a), "l"(b));
}

// ---------------- in-degree histogram: 4 edges/thread, int4 loads ----------
__global__ void k_deg(const int* __restrict__ ei) {
    int base = (blockIdx.x * blockDim.x + threadIdx.x) * 4;
    if (base + 3 < N_EDGES) {
        int4 d4 = *(const int4*)(ei + N_EDGES + base);
        atomicAdd(&g_hist[d4.x], 1);
        atomicAdd(&g_hist[d4.y], 1);
        atomicAdd(&g_hist[d4.z], 1);
        atomicAdd(&g_hist[d4.w], 1);
    } else {
        for (int e = base; e < N_EDGES; e++)
            atomicAdd(&g_hist[ei[N_EDGES + e]], 1);
    }
}

// ---------------- scan pass 1 (+ fused dinv = rsqrt(deg+1)) ----------------
__global__ void k_scan1() {
    __shared__ int sh[SCAN_B];
    int t = threadIdx.x;
    int i = blockIdx.x * SCAN_B + t;
    int v = (i < N_NODES) ? g_hist[i] : 0;
    if (i < N_NODES) g_deg[i] = rsqrtf((float)v + 1.0f);
    sh[t] = v;
    __syncthreads();
    for (int off = 1; off < SCAN_B; off <<= 1) {
        int x = (t >= off) ? sh[t - off] : 0;
        __syncthreads();
        sh[t] += x;
        __syncthreads();
    }
    if (i < N_NODES) g_rowstart[i] = sh[t] - v;
    if (t == SCAN_B - 1) g_bsum[blockIdx.x] = sh[t];
}

// ---------------- scan pass 2+3 fused: block offsets + apply ----------------
__global__ void k_scan3() {
    __shared__ int sb[64];
    int t = threadIdx.x;
    if (t < 64) sb[t] = (t < N_SBLK) ? g_bsum[t] : 0;
    __syncthreads();
#pragma unroll
    for (int off = 1; off < 64; off <<= 1) {
        int x = (t < 64 && t >= off) ? sb[t - off] : 0;
        __syncthreads();
        if (t < 64) sb[t] += x;
        __syncthreads();
    }
    int i = blockIdx.x * blockDim.x + t;
    if (i < N_NODES) {
        int blk = i / SCAN_B;
        int add = blk ? sb[blk - 1] : 0;
        int rs = g_rowstart[i] + add;
        g_rowstart[i] = rs;
        g_cursor[i]   = rs;
    }
}

// ---------------- CSR fill: 4 edges/thread, int4 loads ---------------------
__global__ void k_fill(const int* __restrict__ ei) {
    int base = (blockIdx.x * blockDim.x + threadIdx.x) * 4;
    if (base + 3 < N_EDGES) {
        int4 s4 = *(const int4*)(ei + base);
        int4 d4 = *(const int4*)(ei + N_EDGES + base);
        int p0 = atomicAdd(&g_cursor[d4.x], 1);
        int p1 = atomicAdd(&g_cursor[d4.y], 1);
        int p2 = atomicAdd(&g_cursor[d4.z], 1);
        int p3 = atomicAdd(&g_cursor[d4.w], 1);
        g_csrc[p0] = s4.x;
        g_csrc[p1] = s4.y;
        g_csrc[p2] = s4.z;
        g_csrc[p3] = s4.w;
    } else {
        for (int e = base; e < N_EDGES; e++) {
            int pos = atomicAdd(&g_cursor[ei[N_EDGES + e]], 1);
            g_csrc[pos] = ei[e];
        }
    }
}

// ---------------- GEMM (f32x2) ----------------------------------------------
// Layer 1 (src_sel=0): A read directly from X [128,N] column-major (coalesced);
//                      writes g_xT rows as side-product; g_xw = A@W (raw).
// Layer 2 (src_sel=1): A = g_f1 rows; g_xw = (A@W)*dinv (pre-scaled).
// Block: 128 nodes x 128 cols, 256 threads, 8 nodes x 8 cols per thread.
__global__ void __launch_bounds__(256) k_gemm(int src_sel,
                                              const float* __restrict__ Xg,
                                              const float* __restrict__ W) {
    if (src_sel == 0 && blockIdx.x == 0 && threadIdx.x < D) {
        g_cs[threadIdx.x] = 0.0f;
        g_cs2[threadIdx.x] = 0.0f;
    }
    __shared__ float2 As2[128][16];    // 16 KB: (a,a) pairs, 16-col k-chunk
    __shared__ float  Ws[16][132];     // 8.25 KB padded
    int t  = threadIdx.x;
    int tx = t & 15;                   // column group (8 cols)
    int ty = t >> 4;                   // node group (8 nodes)
    int nbase = blockIdx.x * 128;

    unsigned long long acc[8][4];
#pragma unroll
    for (int i = 0; i < 8; i++)
#pragma unroll
        for (int p = 0; p < 4; p++) acc[i][p] = 0ull;

    for (int fc = 0; fc < D; fc += 16) {
        if (src_sel == 0) {
            // A from X column-major: consecutive threads -> consecutive nodes
#pragma unroll
            for (int k = 0; k < 8; k++) {
                int idx = t + k * 256;
                int c = idx >> 7;              // f within chunk (0..15)
                int r = idx & 127;             // node within tile
                int n = nbase + r;
                float v = (n < N_NODES) ? Xg[(size_t)(fc + c) * N_NODES + n] : 0.0f;
                As2[r][c] = make_float2(v, v);
            }
        } else {
#pragma unroll
            for (int k = 0; k < 8; k++) {
                int idx = t + k * 256;
                int r = idx >> 4, c = idx & 15;
                int n = nbase + r;
                float v = (n < N_NODES) ? g_f1[(size_t)n * D + fc + c] : 0.0f;
                As2[r][c] = make_float2(v, v);
            }
        }
#pragma unroll
        for (int k = 0; k < 8; k++) {           // 16x128 W chunk
            int idx = t + k * 256;
            int r = idx >> 7, c = idx & 127;
            Ws[r][c] = W[(fc + r) * D + c];
        }
        __syncthreads();

        if (src_sel == 0) {
            // write g_xT rows from staged tile (128 nodes x 16 f = 512 float4)
#pragma unroll
            for (int k = 0; k < 2; k++) {
                int idx = t + k * 256;
                int r = idx >> 2;              // node
                int q = idx & 3;               // float4 group
                int n = nbase + r;
                if (n < N_NODES) {
                    float4 v = make_float4(As2[r][q*4].x,   As2[r][q*4+1].x,
                                           As2[r][q*4+2].x, As2[r][q*4+3].x);
                    ((float4*)(g_xT + (size_t)n * D + fc))[q] = v;
                }
            }
        }

#pragma unroll
        for (int ff = 0; ff < 16; ff++) {
            const unsigned long long* wrow =
                (const unsigned long long*)&Ws[ff][tx * 8];
            unsigned long long w0 = wrow[0];
            unsigned long long w1 = wrow[1];
            unsigned long long w2 = wrow[2];
            unsigned long long w3 = wrow[3];
#pragma unroll
            for (int i = 0; i < 8; i++) {
                unsigned long long a2 =
                    *(const unsigned long long*)&As2[ty * 8 + i][ff];
                fma2(acc[i][0], a2, w0);
                fma2(acc[i][1], a2, w1);
                fma2(acc[i][2], a2, w2);
                fma2(acc[i][3], a2, w3);
            }
        }
        __syncthreads();
    }

#pragma unroll
    for (int i = 0; i < 8; i++) {
        int node = nbase + ty * 8 + i;
        if (node >= N_NODES) continue;
        float di = src_sel ? g_deg[node] : 1.0f;
        size_t off = (size_t)node * D + tx * 8;
        float2 p0 = *(float2*)&acc[i][0];
        float2 p1 = *(float2*)&acc[i][1];
        float2 p2 = *(float2*)&acc[i][2];
        float2 p3 = *(float2*)&acc[i][3];
        ((float4*)(g_xw + off))[0] =
            make_float4(p0.x * di, p0.y * di, p1.x * di, p1.y * di);
        ((float4*)(g_xw + off))[1] =
            make_float4(p2.x * di, p2.y * di, p3.x * di, p3.y * di);
    }
}

// ---------------- fused CSR gather + MessageNorm + GELU (+stats) -----------
// stage 0: xw raw   -> msg = dinv[d]*(dinv[d]*xw[d] + sum dinv[s]*xw[s]) + b
// stage 1: xw scaled-> msg = dinv[d]*(xw[d] + sum xw[s]) + b   (+res, +stats)
__global__ void __launch_bounds__(512) k_agg(int stage,
                                             const float* __restrict__ bias,
                                             const float* __restrict__ scale) {
    __shared__ float s_cs[D], s_cs2[D];
    if (stage) {
        if (threadIdx.x < D) { s_cs[threadIdx.x] = 0.0f; s_cs2[threadIdx.x] = 0.0f; }
        __syncthreads();
    }

    int gw = (blockIdx.x * blockDim.x + threadIdx.x) >> 5;
    int lane = threadIdx.x & 31;
    bool active = gw < N_NODES;
    float4 r = make_float4(0.f, 0.f, 0.f, 0.f);

    if (active) {
        const float4* xw4 = (const float4*)g_xw;
        float nd = g_deg[gw];
        float4 acc = xw4[(size_t)gw * 32 + lane];       // self-loop term
        if (!stage) { acc.x *= nd; acc.y *= nd; acc.z *= nd; acc.w *= nd; }
        int rs  = g_rowstart[gw];
        int end = rs + g_hist[gw];
        int e = rs;
        if (stage) {
            for (; e + 8 <= end; e += 8) {
                int s0 = g_csrc[e],     s1 = g_csrc[e + 1];
                int s2 = g_csrc[e + 2], s3 = g_csrc[e + 3];
                int s4 = g_csrc[e + 4], s5 = g_csrc[e + 5];
                int s6 = g_csrc[e + 6], s7 = g_csrc[e + 7];
                float4 v0 = xw4[(size_t)s0 * 32 + lane];
                float4 v1 = xw4[(size_t)s1 * 32 + lane];
                float4 v2 = xw4[(size_t)s2 * 32 + lane];
                float4 v3 = xw4[(size_t)s3 * 32 + lane];
                float4 v4 = xw4[(size_t)s4 * 32 + lane];
                float4 v5 = xw4[(size_t)s5 * 32 + lane];
                float4 v6 = xw4[(size_t)s6 * 32 + lane];
                float4 v7 = xw4[(size_t)s7 * 32 + lane];
                acc.x += ((v0.x + v1.x) + (v2.x + v3.x)) + ((v4.x + v5.x) + (v6.x + v7.x));
                acc.y += ((v0.y + v1.y) + (v2.y + v3.y)) + ((v4.y + v5.y) + (v6.y + v7.y));
                acc.z += ((v0.z + v1.z) + (v2.z + v3.z)) + ((v4.z + v5.z) + (v6.z + v7.z));
                acc.w += ((v0.w + v1.w) + (v2.w + v3.w)) + ((v4.w + v5.w) + (v6.w + v7.w));
            }
            for (; e < end; e++) {
                float4 v = xw4[(size_t)g_csrc[e] * 32 + lane];
                acc.x += v.x; acc.y += v.y; acc.z += v.z; acc.w += v.w;
            }
        } else {
            for (; e + 4 <= end; e += 4) {
                int s0 = g_csrc[e],     s1 = g_csrc[e + 1];
                int s2 = g_csrc[e + 2], s3 = g_csrc[e + 3];
                float n0 = g_deg[s0], n1 = g_deg[s1], n2 = g_deg[s2], n3 = g_deg[s3];
                float4 v0 = xw4[(size_t)s0 * 32 + lane];
                float4 v1 = xw4[(size_t)s1 * 32 + lane];
                float4 v2 = xw4[(size_t)s2 * 32 + lane];
                float4 v3 = xw4[(size_t)s3 * 32 + lane];
                acc.x += (v0.x*n0 + v1.x*n1) + (v2.x*n2 + v3.x*n3);
                acc.y += (v0.y*n0 + v1.y*n1) + (v2.y*n2 + v3.y*n3);
                acc.z += (v0.z*n0 + v1.z*n1) + (v2.z*n2 + v3.z*n3);
                acc.w += (v0.w*n0 + v1.w*n1) + (v2.w*n2 + v3.w*n3);
            }
            for (; e < end; e++) {
                int s0 = g_csrc[e];
                float n0 = g_deg[s0];
                float4 v = xw4[(size_t)s0 * 32 + lane];
                acc.x += v.x*n0; acc.y += v.y*n0; acc.z += v.z*n0; acc.w += v.w*n0;
            }
        }

        float4 bb = ((const float4*)bias)[lane];
        float4 m = make_float4(acc.x * nd + bb.x, acc.y * nd + bb.y,
                               acc.z * nd + bb.z, acc.w * nd + bb.w);

        size_t off = (size_t)gw * D;
        const float* xprev = stage ? g_f1 : g_xT;
        float4 xv = ((const float4*)(xprev + off))[lane];

        float ms = m.x*m.x + m.y*m.y + m.z*m.z + m.w*m.w;
        float xs = xv.x*xv.x + xv.y*xv.y + xv.z*xv.z + xv.w*xv.w;
#pragma unroll
        for (int o = 16; o; o >>= 1) {
            ms += __shfl_xor_sync(0xFFFFFFFFu, ms, o);
            xs += __shfl_xor_sync(0xFFFFFFFFu, xs, o);
        }
        float coef = scale[0] * sqrtf(xs) / fmaxf(sqrtf(ms), 1e-12f);

        r.x = gelu_exact(xv.x + coef * m.x);
        r.y = gelu_exact(xv.y + coef * m.y);
        r.z = gelu_exact(xv.z + coef * m.z);
        r.w = gelu_exact(xv.w + coef * m.w);

        if (stage) {
            float4 rv = ((const float4*)(g_xT + off))[lane];
            r.x += rv.x; r.y += rv.y; r.z += rv.z; r.w += rv.w;
        }
        float* out = stage ? g_y : g_f1;
        ((float4*)(out + off))[lane] = r;
    }

    if (stage) {
        if (active) {
            int c0 = lane * 4;
            atomicAdd(&s_cs [c0    ], r.x); atomicAdd(&s_cs2[c0    ], r.x * r.x);
            atomicAdd(&s_cs [c0 + 1], r.y); atomicAdd(&s_cs2[c0 + 1], r.y * r.y);
            atomicAdd(&s_cs [c0 + 2], r.z); atomicAdd(&s_cs2[c0 + 2], r.z * r.z);
            atomicAdd(&s_cs [c0 + 3], r.w); atomicAdd(&s_cs2[c0 + 3], r.w * r.w);
        }
        __syncthreads();
        if (threadIdx.x < D) {
            atomicAdd(&g_cs [threadIdx.x], s_cs [threadIdx.x]);
            atomicAdd(&g_cs2[threadIdx.x], s_cs2[threadIdx.x]);
        }
    }
}

// ---------------- finalize: GraphNorm + GELU (+ restore g_hist = 0) --------
__global__ void k_final(const float* __restrict__ gnw,
                        const float* __restrict__ gnb,
                        const float* __restrict__ gnm,
                        float* __restrict__ out) {
    const float invN = 1.0f / (float)N_NODES;
    for (int idx = blockIdx.x * blockDim.x + threadIdx.x;
         idx < N_NODES * D; idx += gridDim.x * blockDim.x) {
        if (idx < N_NODES) g_hist[idx] = 0;     // self-restore for next replay
        int c = idx & (D - 1);
        float mean = g_cs[c]  * invN;
        float ey2  = g_cs2[c] * invN;
        float msc  = gnm[c];
        float sub  = g_y[idx] - mean * msc;
        float var  = ey2 - 2.0f * msc * mean * mean + msc * msc * mean * mean;
        float o = gnw[c] * sub * rsqrtf(var + 1e-5f) + gnb[c];
        out[idx] = gelu_exact(o);
    }
}

// ---------------- launch ----------------------------------------------------
extern "C" void kernel_launch(void* const* d_in, const int* in_sizes, int n_in,
                              void* d_out, int out_size) {
    const float* X   = (const float*)d_in[0];
    const int*   ei  = (const int*)  d_in[1];     // int32 (JAX x64 disabled)
    const float* W1  = (const float*)d_in[2];
    const float* b1  = (const float*)d_in[3];
    const float* s1  = (const float*)d_in[4];
    const float* W2  = (const float*)d_in[5];
    const float* b2  = (const float*)d_in[6];
    const float* s2  = (const float*)d_in[7];
    const float* gnw = (const float*)d_in[8];
    const float* gnb = (const float*)d_in[9];
    const float* gnm = (const float*)d_in[10];
    float* out = (float*)d_out;

    const int TB = 256;
    int gemm_blocks = (N_NODES + 127) / 128;
    int agg_blocks  = (N_NODES * 32 + 511) / 512;
    int edge4_blocks = (N_EDGES / 4 + TB - 1) / TB;

    cudaStream_t se;                       // edge-pipeline branch
    cudaStreamCreateWithFlags(&se, cudaStreamNonBlocking);
    cudaEvent_t evFork, evJoin;
    cudaEventCreateWithFlags(&evFork, cudaEventDisableTiming);
    cudaEventCreateWithFlags(&evJoin, cudaEventDisableTiming);

    // fork: edge pipeline on se, dense pipeline on default stream
    cudaEventRecord(evFork, 0);
    cudaStreamWaitEvent(se, evFork, 0);

    // branch A (se): CSR build + dinv
    k_deg   <<<edge4_blocks, TB, 0, se>>>(ei);
    k_scan1 <<<N_SBLK, SCAN_B, 0, se>>>();
    k_scan3 <<<(N_NODES + TB - 1) / TB, TB, 0, se>>>();
    k_fill  <<<edge4_blocks, TB, 0, se>>>(ei);
    cudaEventRecord(evJoin, se);

    // branch B (default): raw GEMM layer 1 (reads X directly, emits g_xT)
    k_gemm <<<gemm_blocks, TB>>>(0, X, W1);

    // join
    cudaStreamWaitEvent(0, evJoin, 0);

    // ---- layer 1 aggregation (applies dinv per edge) ----
    k_agg  <<<agg_blocks, 512>>>(0, b1, s1);

    // ---- layer 2 (pre-scaled path) ----
    k_gemm <<<gemm_blocks, TB>>>(1, X, W2);
    k_agg  <<<agg_blocks, 512>>>(1, b2, s2);

    // ---- GraphNorm + GELU ----
    k_final<<<4096, TB>>>(gnw, gnb, gnm, out);

    cudaEventDestroy(evFork);
    cudaEventDestroy(evJoin);
    cudaStreamDestroy(se);
}

// round 9
// speedup vs baseline: 1.0061x; 1.0061x over previous
#include <cuda_runtime.h>
#include <math.h>

#define N_NODES 50000
#define N_EDGES 800000
#define D 128
#define SCAN_B 1024
#define N_SBLK ((N_NODES + SCAN_B - 1) / SCAN_B)   // 49
#define CHUNK  25000                                // node-range pipeline chunk

// ---------------- scratch (device globals; self-restoring across replays) --
__device__ float g_xT [(size_t)N_NODES * D];   // X transposed: [N,128]
__device__ float g_xw [(size_t)N_NODES * D];   // GEMM out (L1 raw, L2 pre-scaled)
__device__ float g_f1 [(size_t)N_NODES * D];   // layer-1 output
__device__ float g_y  [(size_t)N_NODES * D];   // layer-2 output (+residual)
__device__ float g_deg[N_NODES];               // dinv = rsqrt(1 + in_deg)
__device__ int   g_hist[N_NODES];              // in-degree (zeroed by k_final)
__device__ int   g_rowstart[N_NODES];          // CSR row starts (by dst)
__device__ int   g_cursor[N_NODES];            // fill cursors
__device__ int   g_csrc[N_EDGES];              // CSR src indices
__device__ int   g_bsum[64];                   // scan block sums
__device__ float g_cs [D];                     // col sum of y  (zeroed by gemm L1)
__device__ float g_cs2[D];                     // col sum of y^2

__device__ __forceinline__ float gelu_exact(float v) {
    return v * normcdff(v);     // jax.nn.gelu(approximate=False)
}

__device__ __forceinline__ void fma2(unsigned long long& acc,
                                     unsigned long long a,
                                     unsigned long long b) {
    asm("fma.rn.f32x2 %0, %1, %2, %0;" : "+l"(acc) : "l"(a), "l"(b));
}

// ---------------- in-degree histogram (edge_index is INT32) ----------------
__global__ void k_deg(const int* __restrict__ ei) {
    int e = blockIdx.x * blockDim.x + threadIdx.x;
    if (e < N_EDGES) atomicAdd(&g_hist[ei[N_EDGES + e]], 1);
}

// ---------------- scan pass 1 (+ fused dinv = rsqrt(deg+1)) ----------------
__global__ void k_scan1() {
    __shared__ int sh[SCAN_B];
    int t = threadIdx.x;
    int i = blockIdx.x * SCAN_B + t;
    int v = (i < N_NODES) ? g_hist[i] : 0;
    if (i < N_NODES) g_deg[i] = rsqrtf((float)v + 1.0f);
    sh[t] = v;
    __syncthreads();
    for (int off = 1; off < SCAN_B; off <<= 1) {
        int x = (t >= off) ? sh[t - off] : 0;
        __syncthreads();
        sh[t] += x;
        __syncthreads();
    }
    if (i < N_NODES) g_rowstart[i] = sh[t] - v;
    if (t == SCAN_B - 1) g_bsum[blockIdx.x] = sh[t];
}

// ---------------- scan pass 2+3 fused: block offsets + apply ----------------
__global__ void k_scan3() {
    __shared__ int sb[64];
    int t = threadIdx.x;
    if (t < 64) sb[t] = (t < N_SBLK) ? g_bsum[t] : 0;
    __syncthreads();
#pragma unroll
    for (int off = 1; off < 64; off <<= 1) {
        int x = (t < 64 && t >= off) ? sb[t - off] : 0;
        __syncthreads();
        if (t < 64) sb[t] += x;
        __syncthreads();
    }
    int i = blockIdx.x * blockDim.x + t;
    if (i < N_NODES) {
        int blk = i / SCAN_B;
        int add = blk ? sb[blk - 1] : 0;
        int rs = g_rowstart[i] + add;
        g_rowstart[i] = rs;
        g_cursor[i]   = rs;
    }
}

// ---------------- CSR fill ---------------------------------------------------
__global__ void k_fill(const int* __restrict__ ei) {
    int e = blockIdx.x * blockDim.x + threadIdx.x;
    if (e < N_EDGES) {
        int s = ei[e];
        int d = ei[N_EDGES + e];
        int pos = atomicAdd(&g_cursor[d], 1);
        g_csrc[pos] = s;
    }
}

// ---------------- transpose X [128,N] -> xT [N,128] ------------------------
__global__ void k_transpose(const float* __restrict__ X) {
    __shared__ float s[32][33];
    int n0 = blockIdx.x * 32;
    int f0 = blockIdx.y * 32;
    int tx = threadIdx.x, ty = threadIdx.y;          // (32, 8)
    int n = n0 + tx;
#pragma unroll
    for (int i = 0; i < 4; i++) {
        int f = f0 + ty + i * 8;
        if (n < N_NODES) s[ty + i * 8][tx] = X[(size_t)f * N_NODES + n];
    }
    __syncthreads();
#pragma unroll
    for (int i = 0; i < 4; i++) {
        int n2 = n0 + ty + i * 8;
        int f2 = f0 + tx;
        if (n2 < N_NODES) g_xT[(size_t)n2 * D + f2] = s[tx][ty + i * 8];
    }
}

// ---------------- GEMM (f32x2) ----------------------------------------------
// Layer 1 (src_sel=0): g_xw = A @ W          (raw; dinv applied in agg stage 0)
// Layer 2 (src_sel=1): g_xw = (A @ W)*dinv   (pre-scaled fast path)
// Node range [node0, node0+ncount). Block: 128 nodes x 128 cols, 256 threads.
__global__ void __launch_bounds__(256) k_gemm(int src_sel, int node0, int ncount,
                                              const float* __restrict__ W) {
    const float* __restrict__ A = src_sel ? g_f1 : g_xT;
    if (src_sel == 0 && blockIdx.x == 0 && threadIdx.x < D) {
        g_cs[threadIdx.x] = 0.0f;
        g_cs2[threadIdx.x] = 0.0f;
    }
    __shared__ float2 As2[128][16];    // 16 KB: (a,a) pairs, 16-col k-chunk
    __shared__ float  Ws[16][132];     // 8.25 KB padded
    int t  = threadIdx.x;
    int tx = t & 15;                   // column group (8 cols)
    int ty = t >> 4;                   // node group (8 nodes)
    int nbase = node0 + blockIdx.x * 128;
    int nlimit = node0 + ncount;

    unsigned long long acc[8][4];
#pragma unroll
    for (int i = 0; i < 8; i++)
#pragma unroll
        for (int p = 0; p < 4; p++) acc[i][p] = 0ull;

    for (int fc = 0; fc < D; fc += 16) {
#pragma unroll
        for (int k = 0; k < 8; k++) {           // 128x16 A chunk (dup pairs)
            int idx = t + k * 256;
            int r = idx >> 4, c = idx & 15;
            int n = nbase + r;
            float v = (n < nlimit) ? A[(size_t)n * D + fc + c] : 0.0f;
            As2[r][c] = make_float2(v, v);
        }
#pragma unroll
        for (int k = 0; k < 8; k++) {           // 16x128 W chunk
            int idx = t + k * 256;
            int r = idx >> 7, c = idx & 127;
            Ws[r][c] = W[(fc + r) * D + c];
        }
        __syncthreads();
#pragma unroll
        for (int ff = 0; ff < 16; ff++) {
            const unsigned long long* wrow =
                (const unsigned long long*)&Ws[ff][tx * 8];
            unsigned long long w0 = wrow[0];
            unsigned long long w1 = wrow[1];
            unsigned long long w2 = wrow[2];
            unsigned long long w3 = wrow[3];
#pragma unroll
            for (int i = 0; i < 8; i++) {
                unsigned long long a2 =
                    *(const unsigned long long*)&As2[ty * 8 + i][ff];
                fma2(acc[i][0], a2, w0);
                fma2(acc[i][1], a2, w1);
                fma2(acc[i][2], a2, w2);
                fma2(acc[i][3], a2, w3);
            }
        }
        __syncthreads();
    }

#pragma unroll
    for (int i = 0; i < 8; i++) {
        int node = nbase + ty * 8 + i;
        if (node >= nlimit) continue;
        float di = src_sel ? g_deg[node] : 1.0f;
        size_t off = (size_t)node * D + tx * 8;
        float2 p0 = *(float2*)&acc[i][0];
        float2 p1 = *(float2*)&acc[i][1];
        float2 p2 = *(float2*)&acc[i][2];
        float2 p3 = *(float2*)&acc[i][3];
        ((float4*)(g_xw + off))[0] =
            make_float4(p0.x * di, p0.y * di, p1.x * di, p1.y * di);
        ((float4*)(g_xw + off))[1] =
            make_float4(p2.x * di, p2.y * di, p3.x * di, p3.y * di);
    }
}

// ---------------- fused CSR gather + MessageNorm + GELU (+stats) -----------
// stage 0: xw raw   -> msg = dinv[d]*(dinv[d]*xw[d] + sum dinv[s]*xw[s]) + b
// stage 1: xw scaled-> msg = dinv[d]*(xw[d] + sum xw[s]) + b   (+res, +stats)
// Node range [node0, node0+ncount).
__global__ void __launch_bounds__(512) k_agg(int stage, int node0, int ncount,
                                             const float* __restrict__ bias,
                                             const float* __restrict__ scale) {
    __shared__ float s_cs[D], s_cs2[D];
    if (stage) {
        if (threadIdx.x < D) { s_cs[threadIdx.x] = 0.0f; s_cs2[threadIdx.x] = 0.0f; }
        __syncthreads();
    }

    int gw = node0 + ((blockIdx.x * blockDim.x + threadIdx.x) >> 5);
    int lane = threadIdx.x & 31;
    bool active = gw < node0 + ncount;
    float4 r = make_float4(0.f, 0.f, 0.f, 0.f);

    if (active) {
        const float4* xw4 = (const float4*)g_xw;
        float nd = g_deg[gw];
        float4 acc = xw4[(size_t)gw * 32 + lane];       // self-loop term
        if (!stage) { acc.x *= nd; acc.y *= nd; acc.z *= nd; acc.w *= nd; }
        int rs  = g_rowstart[gw];
        int end = rs + g_hist[gw];
        int e = rs;
        if (stage) {
            for (; e + 8 <= end; e += 8) {
                int s0 = g_csrc[e],     s1 = g_csrc[e + 1];
                int s2 = g_csrc[e + 2], s3 = g_csrc[e + 3];
                int s4 = g_csrc[e + 4], s5 = g_csrc[e + 5];
                int s6 = g_csrc[e + 6], s7 = g_csrc[e + 7];
                float4 v0 = xw4[(size_t)s0 * 32 + lane];
                float4 v1 = xw4[(size_t)s1 * 32 + lane];
                float4 v2 = xw4[(size_t)s2 * 32 + lane];
                float4 v3 = xw4[(size_t)s3 * 32 + lane];
                float4 v4 = xw4[(size_t)s4 * 32 + lane];
                float4 v5 = xw4[(size_t)s5 * 32 + lane];
                float4 v6 = xw4[(size_t)s6 * 32 + lane];
                float4 v7 = xw4[(size_t)s7 * 32 + lane];
                acc.x += ((v0.x + v1.x) + (v2.x + v3.x)) + ((v4.x + v5.x) + (v6.x + v7.x));
                acc.y += ((v0.y + v1.y) + (v2.y + v3.y)) + ((v4.y + v5.y) + (v6.y + v7.y));
                acc.z += ((v0.z + v1.z) + (v2.z + v3.z)) + ((v4.z + v5.z) + (v6.z + v7.z));
                acc.w += ((v0.w + v1.w) + (v2.w + v3.w)) + ((v4.w + v5.w) + (v6.w + v7.w));
            }
            for (; e < end; e++) {
                float4 v = xw4[(size_t)g_csrc[e] * 32 + lane];
                acc.x += v.x; acc.y += v.y; acc.z += v.z; acc.w += v.w;
            }
        } else {
            for (; e + 4 <= end; e += 4) {
                int s0 = g_csrc[e],     s1 = g_csrc[e + 1];
                int s2 = g_csrc[e + 2], s3 = g_csrc[e + 3];
                float n0 = g_deg[s0], n1 = g_deg[s1], n2 = g_deg[s2], n3 = g_deg[s3];
                float4 v0 = xw4[(size_t)s0 * 32 + lane];
                float4 v1 = xw4[(size_t)s1 * 32 + lane];
                float4 v2 = xw4[(size_t)s2 * 32 + lane];
                float4 v3 = xw4[(size_t)s3 * 32 + lane];
                acc.x += (v0.x*n0 + v1.x*n1) + (v2.x*n2 + v3.x*n3);
                acc.y += (v0.y*n0 + v1.y*n1) + (v2.y*n2 + v3.y*n3);
                acc.z += (v0.z*n0 + v1.z*n1) + (v2.z*n2 + v3.z*n3);
                acc.w += (v0.w*n0 + v1.w*n1) + (v2.w*n2 + v3.w*n3);
            }
            for (; e < end; e++) {
                int s0 = g_csrc[e];
                float n0 = g_deg[s0];
                float4 v = xw4[(size_t)s0 * 32 + lane];
                acc.x += v.x*n0; acc.y += v.y*n0; acc.z += v.z*n0; acc.w += v.w*n0;
            }
        }

        float4 bb = ((const float4*)bias)[lane];
        float4 m = make_float4(acc.x * nd + bb.x, acc.y * nd + bb.y,
                               acc.z * nd + bb.z, acc.w * nd + bb.w);

        size_t off = (size_t)gw * D;
        const float* xprev = stage ? g_f1 : g_xT;
        float4 xv = ((const float4*)(xprev + off))[lane];

        float ms = m.x*m.x + m.y*m.y + m.z*m.z + m.w*m.w;
        float xs = xv.x*xv.x + xv.y*xv.y + xv.z*xv.z + xv.w*xv.w;
#pragma unroll
        for (int o = 16; o; o >>= 1) {
            ms += __shfl_xor_sync(0xFFFFFFFFu, ms, o);
            xs += __shfl_xor_sync(0xFFFFFFFFu, xs, o);
        }
        float coef = scale[0] * sqrtf(xs) / fmaxf(sqrtf(ms), 1e-12f);

        r.x = gelu_exact(xv.x + coef * m.x);
        r.y = gelu_exact(xv.y + coef * m.y);
        r.z = gelu_exact(xv.z + coef * m.z);
        r.w = gelu_exact(xv.w + coef * m.w);

        if (stage) {
            float4 rv = ((const float4*)(g_xT + off))[lane];
            r.x += rv.x; r.y += rv.y; r.z += rv.z; r.w += rv.w;
        }
        float* out = stage ? g_y : g_f1;
        ((float4*)(out + off))[lane] = r;
    }

    if (stage) {
        if (active) {
            int c0 = lane * 4;
            atomicAdd(&s_cs [c0    ], r.x); atomicAdd(&s_cs2[c0    ], r.x * r.x);
            atomicAdd(&s_cs [c0 + 1], r.y); atomicAdd(&s_cs2[c0 + 1], r.y * r.y);
            atomicAdd(&s_cs [c0 + 2], r.z); atomicAdd(&s_cs2[c0 + 2], r.z * r.z);
            atomicAdd(&s_cs [c0 + 3], r.w); atomicAdd(&s_cs2[c0 + 3], r.w * r.w);
        }
        __syncthreads();
        if (threadIdx.x < D) {
            atomicAdd(&g_cs [threadIdx.x], s_cs [threadIdx.x]);
            atomicAdd(&g_cs2[threadIdx.x], s_cs2[threadIdx.x]);
        }
    }
}

// ---------------- finalize: GraphNorm + GELU (+ restore g_hist = 0) --------
__global__ void k_final(const float* __restrict__ gnw,
                        const float* __restrict__ gnb,
                        const float* __restrict__ gnm,
                        float* __restrict__ out) {
    const float invN = 1.0f / (float)N_NODES;
    for (int idx = blockIdx.x * blockDim.x + threadIdx.x;
         idx < N_NODES * D; idx += gridDim.x * blockDim.x) {
        if (idx < N_NODES) g_hist[idx] = 0;     // self-restore for next replay
        int c = idx & (D - 1);
        float mean = g_cs[c]  * invN;
        float ey2  = g_cs2[c] * invN;
        float msc  = gnm[c];
        float sub  = g_y[idx] - mean * msc;
        float var  = ey2 - 2.0f * msc * mean * mean + msc * msc * mean * mean;
        float o = gnw[c] * sub * rsqrtf(var + 1e-5f) + gnb[c];
        out[idx] = gelu_exact(o);
    }
}

// ---------------- launch ----------------------------------------------------
extern "C" void kernel_launch(void* const* d_in, const int* in_sizes, int n_in,
                              void* d_out, int out_size) {
    const float* X   = (const float*)d_in[0];
    const int*   ei  = (const int*)  d_in[1];     // int32 (JAX x64 disabled)
    const float* W1  = (const float*)d_in[2];
    const float* b1  = (const float*)d_in[3];
    const float* s1  = (const float*)d_in[4];
    const float* W2  = (const float*)d_in[5];
    const float* b2  = (const float*)d_in[6];
    const float* s2  = (const float*)d_in[7];
    const float* gnw = (const float*)d_in[8];
    const float* gnb = (const float*)d_in[9];
    const float* gnm = (const float*)d_in[10];
    float* out = (float*)d_out;

    const int TB = 256;
    const int C0 = CHUNK, C1 = N_NODES - CHUNK;
    int gemm_blocks_full = (N_NODES + 127) / 128;
    int gemm_blocks_c0   = (C0 + 127) / 128;
    int gemm_blocks_c1   = (C1 + 127) / 128;
    int agg_blocks_full  = (N_NODES * 32 + 511) / 512;
    int agg_blocks_c0    = (C0 * 32 + 511) / 512;
    int agg_blocks_c1    = (C1 * 32 + 511) / 512;
    dim3 tg((N_NODES + 31) / 32, D / 32);

    cudaStream_t se, sp;                   // edge branch, pipeline branch
    cudaStreamCreateWithFlags(&se, cudaStreamNonBlocking);
    cudaStreamCreateWithFlags(&sp, cudaStreamNonBlocking);
    cudaEvent_t evFork, evJoin, evA0, evA1, evG;
    cudaEventCreateWithFlags(&evFork, cudaEventDisableTiming);
    cudaEventCreateWithFlags(&evJoin, cudaEventDisableTiming);
    cudaEventCreateWithFlags(&evA0,   cudaEventDisableTiming);
    cudaEventCreateWithFlags(&evA1,   cudaEventDisableTiming);
    cudaEventCreateWithFlags(&evG,    cudaEventDisableTiming);

    // fork: edge pipeline on se, dense pipeline on default stream
    cudaEventRecord(evFork, 0);
    cudaStreamWaitEvent(se, evFork, 0);
    cudaStreamWaitEvent(sp, evFork, 0);

    // branch A (se): CSR build + dinv (R7-proven 1-edge/thread forms)
    k_deg   <<<(N_EDGES + TB - 1) / TB, TB, 0, se>>>(ei);
    k_scan1 <<<N_SBLK, SCAN_B, 0, se>>>();
    k_scan3 <<<(N_NODES + TB - 1) / TB, TB, 0, se>>>();
    k_fill  <<<(N_EDGES + TB - 1) / TB, TB, 0, se>>>(ei);
    cudaEventRecord(evJoin, se);

    // branch B (default): transpose + raw GEMM layer 1 (full range)
    k_transpose<<<tg, dim3(32, 8)>>>(X);
    k_gemm <<<gemm_blocks_full, TB>>>(0, 0, N_NODES, W1);

    // join edge pipeline
    cudaStreamWaitEvent(0, evJoin, 0);

    // ---- layer 1 agg / layer 2 gemm: 2-chunk software pipeline ----
    k_agg  <<<agg_blocks_c0, 512>>>(0, 0, C0, b1, s1);
    cudaEventRecord(evA0, 0);
    k_agg  <<<agg_blocks_c1, 512>>>(0, C0, C1, b1, s1);
    cudaEventRecord(evA1, 0);

    cudaStreamWaitEvent(sp, evA0, 0);
    k_gemm <<<gemm_blocks_c0, TB, 0, sp>>>(1, 0, C0, W2);
    cudaStreamWaitEvent(sp, evA1, 0);
    k_gemm <<<gemm_blocks_c1, TB, 0, sp>>>(1, C0, C1, W2);
    cudaEventRecord(evG, sp);

    // ---- layer 2 aggregation (needs all of xw) ----
    cudaStreamWaitEvent(0, evG, 0);
    k_agg  <<<agg_blocks_full, 512>>>(1, 0, N_NODES, b2, s2);

    // ---- GraphNorm + GELU ----
    k_final<<<4096, TB>>>(gnw, gnb, gnm, out);

    cudaEventDestroy(evFork);
    cudaEventDestroy(evJoin);
    cudaEventDestroy(evA0);
    cudaEventDestroy(evA1);
    cudaEventDestroy(evG);
    cudaStreamDestroy(se);
    cudaStreamDestroy(sp);
}

// round 10
// speedup vs baseline: 1.1075x; 1.1008x over previous
#include <cuda_runtime.h>
#include <cuda_fp16.h>
#include <math.h>

#define N_NODES 50000
#define N_EDGES 800000
#define D 128
#define SCAN_B 1024
#define N_SBLK ((N_NODES + SCAN_B - 1) / SCAN_B)   // 49

// ---------------- scratch (device globals; self-restoring across replays) --
__device__ float g_xT [(size_t)N_NODES * D];   // X transposed: [N,128]
__device__ uint2 g_xwh[(size_t)N_NODES * 32];  // GEMM out, fp16x2 packed (128 h/row)
__device__ float g_f1 [(size_t)N_NODES * D];   // layer-1 output (fp32)
__device__ float g_y  [(size_t)N_NODES * D];   // layer-2 output (+residual)
__device__ float g_deg[N_NODES];               // dinv = rsqrt(1 + in_deg)
__device__ int   g_hist[N_NODES];              // in-degree (zeroed by k_final)
__device__ int   g_rowstart[N_NODES];          // CSR row starts (by dst)
__device__ int   g_cursor[N_NODES];            // fill cursors
__device__ int   g_csrc[N_EDGES];              // CSR src indices
__device__ int   g_bsum[64];                   // scan block sums
__device__ float g_cs [D];                     // col sum of y  (zeroed by gemm L1)
__device__ float g_cs2[D];                     // col sum of y^2

__device__ __forceinline__ float gelu_exact(float v) {
    return v * normcdff(v);     // jax.nn.gelu(approximate=False)
}

__device__ __forceinline__ void fma2(unsigned long long& acc,
                                     unsigned long long a,
                                     unsigned long long b) {
    asm("fma.rn.f32x2 %0, %1, %2, %0;" : "+l"(acc) : "l"(a), "l"(b));
}

__device__ __forceinline__ float4 up4(uint2 u) {   // unpack 4 halves -> fp32
    float2 f0 = __half22float2(*reinterpret_cast<__half2*>(&u.x));
    float2 f1 = __half22float2(*reinterpret_cast<__half2*>(&u.y));
    return make_float4(f0.x, f0.y, f1.x, f1.y);
}

// ---------------- in-degree histogram (edge_index is INT32) ----------------
__global__ void k_deg(const int* __restrict__ ei) {
    int e = blockIdx.x * blockDim.x + threadIdx.x;
    if (e < N_EDGES) atomicAdd(&g_hist[ei[N_EDGES + e]], 1);
}

// ---------------- scan pass 1 (+ fused dinv = rsqrt(deg+1)) ----------------
__global__ void k_scan1() {
    __shared__ int sh[SCAN_B];
    int t = threadIdx.x;
    int i = blockIdx.x * SCAN_B + t;
    int v = (i < N_NODES) ? g_hist[i] : 0;
    if (i < N_NODES) g_deg[i] = rsqrtf((float)v + 1.0f);
    sh[t] = v;
    __syncthreads();
    for (int off = 1; off < SCAN_B; off <<= 1) {
        int x = (t >= off) ? sh[t - off] : 0;
        __syncthreads();
        sh[t] += x;
        __syncthreads();
    }
    if (i < N_NODES) g_rowstart[i] = sh[t] - v;
    if (t == SCAN_B - 1) g_bsum[blockIdx.x] = sh[t];
}

// ---------------- scan pass 2+3 fused: block offsets + apply ----------------
__global__ void k_scan3() {
    __shared__ int sb[64];
    int t = threadIdx.x;
    if (t < 64) sb[t] = (t < N_SBLK) ? g_bsum[t] : 0;
    __syncthreads();
#pragma unroll
    for (int off = 1; off < 64; off <<= 1) {
        int x = (t < 64 && t >= off) ? sb[t - off] : 0;
        __syncthreads();
        if (t < 64) sb[t] += x;
        __syncthreads();
    }
    int i = blockIdx.x * blockDim.x + t;
    if (i < N_NODES) {
        int blk = i / SCAN_B;
        int add = blk ? sb[blk - 1] : 0;
        int rs = g_rowstart[i] + add;
        g_rowstart[i] = rs;
        g_cursor[i]   = rs;
    }
}

// ---------------- CSR fill ---------------------------------------------------
__global__ void k_fill(const int* __restrict__ ei) {
    int e = blockIdx.x * blockDim.x + threadIdx.x;
    if (e < N_EDGES) {
        int s = ei[e];
        int d = ei[N_EDGES + e];
        int pos = atomicAdd(&g_cursor[d], 1);
        g_csrc[pos] = s;
    }
}

// ---------------- transpose X [128,N] -> xT [N,128] ------------------------
__global__ void k_transpose(const float* __restrict__ X) {
    __shared__ float s[32][33];
    int n0 = blockIdx.x * 32;
    int f0 = blockIdx.y * 32;
    int tx = threadIdx.x, ty = threadIdx.y;          // (32, 8)
    int n = n0 + tx;
#pragma unroll
    for (int i = 0; i < 4; i++) {
        int f = f0 + ty + i * 8;
        if (n < N_NODES) s[ty + i * 8][tx] = X[(size_t)f * N_NODES + n];
    }
    __syncthreads();
#pragma unroll
    for (int i = 0; i < 4; i++) {
        int n2 = n0 + ty + i * 8;
        int f2 = f0 + tx;
        if (n2 < N_NODES) g_xT[(size_t)n2 * D + f2] = s[tx][ty + i * 8];
    }
}

// ---------------- GEMM (f32x2) -> fp16x2 packed output ---------------------
// Layer 1 (src_sel=0): g_xwh = half(A @ W)          (raw; dinv in agg stage 0)
// Layer 2 (src_sel=1): g_xwh = half((A @ W)*dinv)   (pre-scaled fast path)
// Block: 128 nodes x 128 cols, 256 threads, 8 nodes x 8 cols per thread.
__global__ void __launch_bounds__(256) k_gemm(int src_sel,
                                              const float* __restrict__ W) {
    const float* __restrict__ A = src_sel ? g_f1 : g_xT;
    if (src_sel == 0 && blockIdx.x == 0 && threadIdx.x < D) {
        g_cs[threadIdx.x] = 0.0f;
        g_cs2[threadIdx.x] = 0.0f;
    }
    __shared__ float2 As2[128][16];    // 16 KB: (a,a) pairs, 16-col k-chunk
    __shared__ float  Ws[16][132];     // 8.25 KB padded
    int t  = threadIdx.x;
    int tx = t & 15;                   // column group (8 cols)
    int ty = t >> 4;                   // node group (8 nodes)
    int nbase = blockIdx.x * 128;

    unsigned long long acc[8][4];
#pragma unroll
    for (int i = 0; i < 8; i++)
#pragma unroll
        for (int p = 0; p < 4; p++) acc[i][p] = 0ull;

    for (int fc = 0; fc < D; fc += 16) {
#pragma unroll
        for (int k = 0; k < 8; k++) {           // 128x16 A chunk (dup pairs)
            int idx = t + k * 256;
            int r = idx >> 4, c = idx & 15;
            int n = nbase + r;
            float v = (n < N_NODES) ? A[(size_t)n * D + fc + c] : 0.0f;
            As2[r][c] = make_float2(v, v);
        }
#pragma unroll
        for (int k = 0; k < 8; k++) {           // 16x128 W chunk
            int idx = t + k * 256;
            int r = idx >> 7, c = idx & 127;
            Ws[r][c] = W[(fc + r) * D + c];
        }
        __syncthreads();
#pragma unroll
        for (int ff = 0; ff < 16; ff++) {
            const unsigned long long* wrow =
                (const unsigned long long*)&Ws[ff][tx * 8];
            unsigned long long w0 = wrow[0];
            unsigned long long w1 = wrow[1];
            unsigned long long w2 = wrow[2];
            unsigned long long w3 = wrow[3];
#pragma unroll
            for (int i = 0; i < 8; i++) {
                unsigned long long a2 =
                    *(const unsigned long long*)&As2[ty * 8 + i][ff];
                fma2(acc[i][0], a2, w0);
                fma2(acc[i][1], a2, w1);
                fma2(acc[i][2], a2, w2);
                fma2(acc[i][3], a2, w3);
            }
        }
        __syncthreads();
    }

#pragma unroll
    for (int i = 0; i < 8; i++) {
        int node = nbase + ty * 8 + i;
        if (node >= N_NODES) continue;
        float di = src_sel ? g_deg[node] : 1.0f;
        float2 p0 = *(float2*)&acc[i][0];
        float2 p1 = *(float2*)&acc[i][1];
        float2 p2 = *(float2*)&acc[i][2];
        float2 p3 = *(float2*)&acc[i][3];
        __half2 h0 = __floats2half2_rn(p0.x * di, p0.y * di);
        __half2 h1 = __floats2half2_rn(p1.x * di, p1.y * di);
        __half2 h2 = __floats2half2_rn(p2.x * di, p2.y * di);
        __half2 h3 = __floats2half2_rn(p3.x * di, p3.y * di);
        uint4 pk;
        pk.x = *reinterpret_cast<unsigned*>(&h0);
        pk.y = *reinterpret_cast<unsigned*>(&h1);
        pk.z = *reinterpret_cast<unsigned*>(&h2);
        pk.w = *reinterpret_cast<unsigned*>(&h3);
        ((uint4*)g_xwh)[(size_t)node * 16 + tx] = pk;
    }
}

// ---------------- fused CSR gather(fp16) + MessageNorm + GELU (+stats) -----
// stage 0: msg = dinv[d]*(dinv[d]*xw[d] + sum dinv[s]*xw[s]) + b
// stage 1: msg = dinv[d]*(xw[d] + sum xw[s]) + b   (+residual, +stats)
__global__ void __launch_bounds__(512, 2) k_agg(int stage,
                                                const float* __restrict__ bias,
                                                const float* __restrict__ scale) {
    __shared__ float s_cs[D], s_cs2[D];
    if (stage) {
        if (threadIdx.x < D) { s_cs[threadIdx.x] = 0.0f; s_cs2[threadIdx.x] = 0.0f; }
        __syncthreads();
    }

    int gw = (blockIdx.x * blockDim.x + threadIdx.x) >> 5;
    int lane = threadIdx.x & 31;
    bool active = gw < N_NODES;
    float4 r = make_float4(0.f, 0.f, 0.f, 0.f);

    if (active) {
        const uint2* xw2 = (const uint2*)g_xwh;
        float nd = g_deg[gw];
        float4 acc = up4(xw2[(size_t)gw * 32 + lane]);  // self-loop term
        if (!stage) { acc.x *= nd; acc.y *= nd; acc.z *= nd; acc.w *= nd; }
        int rs  = g_rowstart[gw];
        int end = rs + g_hist[gw];
        int e = rs;
        if (stage) {
            for (; e + 8 <= end; e += 8) {
                int s0 = g_csrc[e],     s1 = g_csrc[e + 1];
                int s2 = g_csrc[e + 2], s3 = g_csrc[e + 3];
                int s4 = g_csrc[e + 4], s5 = g_csrc[e + 5];
                int s6 = g_csrc[e + 6], s7 = g_csrc[e + 7];
                float4 v0 = up4(xw2[(size_t)s0 * 32 + lane]);
                float4 v1 = up4(xw2[(size_t)s1 * 32 + lane]);
                float4 v2 = up4(xw2[(size_t)s2 * 32 + lane]);
                float4 v3 = up4(xw2[(size_t)s3 * 32 + lane]);
                float4 v4 = up4(xw2[(size_t)s4 * 32 + lane]);
                float4 v5 = up4(xw2[(size_t)s5 * 32 + lane]);
                float4 v6 = up4(xw2[(size_t)s6 * 32 + lane]);
                float4 v7 = up4(xw2[(size_t)s7 * 32 + lane]);
                acc.x += ((v0.x + v1.x) + (v2.x + v3.x)) + ((v4.x + v5.x) + (v6.x + v7.x));
                acc.y += ((v0.y + v1.y) + (v2.y + v3.y)) + ((v4.y + v5.y) + (v6.y + v7.y));
                acc.z += ((v0.z + v1.z) + (v2.z + v3.z)) + ((v4.z + v5.z) + (v6.z + v7.z));
                acc.w += ((v0.w + v1.w) + (v2.w + v3.w)) + ((v4.w + v5.w) + (v6.w + v7.w));
            }
            for (; e < end; e++) {
                float4 v = up4(xw2[(size_t)g_csrc[e] * 32 + lane]);
                acc.x += v.x; acc.y += v.y; acc.z += v.z; acc.w += v.w;
            }
        } else {
            for (; e + 4 <= end; e += 4) {
                int s0 = g_csrc[e],     s1 = g_csrc[e + 1];
                int s2 = g_csrc[e + 2], s3 = g_csrc[e + 3];
                float n0 = g_deg[s0], n1 = g_deg[s1], n2 = g_deg[s2], n3 = g_deg[s3];
                float4 v0 = up4(xw2[(size_t)s0 * 32 + lane]);
                float4 v1 = up4(xw2[(size_t)s1 * 32 + lane]);
                float4 v2 = up4(xw2[(size_t)s2 * 32 + lane]);
                float4 v3 = up4(xw2[(size_t)s3 * 32 + lane]);
                acc.x += (v0.x*n0 + v1.x*n1) + (v2.x*n2 + v3.x*n3);
                acc.y += (v0.y*n0 + v1.y*n1) + (v2.y*n2 + v3.y*n3);
                acc.z += (v0.z*n0 + v1.z*n1) + (v2.z*n2 + v3.z*n3);
                acc.w += (v0.w*n0 + v1.w*n1) + (v2.w*n2 + v3.w*n3);
            }
            for (; e < end; e++) {
                int s0 = g_csrc[e];
                float n0 = g_deg[s0];
                float4 v = up4(xw2[(size_t)s0 * 32 + lane]);
                acc.x += v.x*n0; acc.y += v.y*n0; acc.z += v.z*n0; acc.w += v.w*n0;
            }
        }

        float4 bb = ((const float4*)bias)[lane];
        float4 m = make_float4(acc.x * nd + bb.x, acc.y * nd + bb.y,
                               acc.z * nd + bb.z, acc.w * nd + bb.w);

        size_t off = (size_t)gw * D;
        const float* xprev = stage ? g_f1 : g_xT;
        float4 xv = ((const float4*)(xprev + off))[lane];

        float ms = m.x*m.x + m.y*m.y + m.z*m.z + m.w*m.w;
        float xs = xv.x*xv.x + xv.y*xv.y + xv.z*xv.z + xv.w*xv.w;
#pragma unroll
        for (int o = 16; o; o >>= 1) {
            ms += __shfl_xor_sync(0xFFFFFFFFu, ms, o);
            xs += __shfl_xor_sync(0xFFFFFFFFu, xs, o);
        }
        float coef = scale[0] * sqrtf(xs) / fmaxf(sqrtf(ms), 1e-12f);

        r.x = gelu_exact(xv.x + coef * m.x);
        r.y = gelu_exact(xv.y + coef * m.y);
        r.z = gelu_exact(xv.z + coef * m.z);
        r.w = gelu_exact(xv.w + coef * m.w);

        if (stage) {
            float4 rv = ((const float4*)(g_xT + off))[lane];
            r.x += rv.x; r.y += rv.y; r.z += rv.z; r.w += rv.w;
        }
        float* out = stage ? g_y : g_f1;
        ((float4*)(out + off))[lane] = r;
    }

    if (stage) {
        if (active) {
            int c0 = lane * 4;
            atomicAdd(&s_cs [c0    ], r.x); atomicAdd(&s_cs2[c0    ], r.x * r.x);
            atomicAdd(&s_cs [c0 + 1], r.y); atomicAdd(&s_cs2[c0 + 1], r.y * r.y);
            atomicAdd(&s_cs [c0 + 2], r.z); atomicAdd(&s_cs2[c0 + 2], r.z * r.z);
            atomicAdd(&s_cs [c0 + 3], r.w); atomicAdd(&s_cs2[c0 + 3], r.w * r.w);
        }
        __syncthreads();
        if (threadIdx.x < D) {
            atomicAdd(&g_cs [threadIdx.x], s_cs [threadIdx.x]);
            atomicAdd(&g_cs2[threadIdx.x], s_cs2[threadIdx.x]);
        }
    }
}

// ---------------- finalize: GraphNorm + GELU (+ restore g_hist = 0) --------
__global__ void k_final(const float* __restrict__ gnw,
                        const float* __restrict__ gnb,
                        const float* __restrict__ gnm,
                        float* __restrict__ out) {
    const float invN = 1.0f / (float)N_NODES;
    for (int idx = blockIdx.x * blockDim.x + threadIdx.x;
         idx < N_NODES * D; idx += gridDim.x * blockDim.x) {
        if (idx < N_NODES) g_hist[idx] = 0;     // self-restore for next replay
        int c = idx & (D - 1);
        float mean = g_cs[c]  * invN;
        float ey2  = g_cs2[c] * invN;
        float msc  = gnm[c];
        float sub  = g_y[idx] - mean * msc;
        float var  = ey2 - 2.0f * msc * mean * mean + msc * msc * mean * mean;
        float o = gnw[c] * sub * rsqrtf(var + 1e-5f) + gnb[c];
        out[idx] = gelu_exact(o);
    }
}

// ---------------- launch ----------------------------------------------------
extern "C" void kernel_launch(void* const* d_in, const int* in_sizes, int n_in,
                              void* d_out, int out_size) {
    const float* X   = (const float*)d_in[0];
    const int*   ei  = (const int*)  d_in[1];     // int32 (JAX x64 disabled)
    const float* W1  = (const float*)d_in[2];
    const float* b1  = (const float*)d_in[3];
    const float* s1  = (const float*)d_in[4];
    const float* W2  = (const float*)d_in[5];
    const float* b2  = (const float*)d_in[6];
    const float* s2  = (const float*)d_in[7];
    const float* gnw = (const float*)d_in[8];
    const float* gnb = (const float*)d_in[9];
    const float* gnm = (const float*)d_in[10];
    float* out = (float*)d_out;

    const int TB = 256;
    int gemm_blocks = (N_NODES + 127) / 128;
    int agg_blocks  = (N_NODES * 32 + 511) / 512;
    dim3 tg((N_NODES + 31) / 32, D / 32);

    cudaStream_t se;                       // edge-pipeline branch
    cudaStreamCreateWithFlags(&se, cudaStreamNonBlocking);
    cudaEvent_t evFork, evJoin;
    cudaEventCreateWithFlags(&evFork, cudaEventDisableTiming);
    cudaEventCreateWithFlags(&evJoin, cudaEventDisableTiming);

    // fork: edge pipeline on se, dense pipeline on default stream
    cudaEventRecord(evFork, 0);
    cudaStreamWaitEvent(se, evFork, 0);

    // branch A (se): CSR build + dinv
    k_deg   <<<(N_EDGES + TB - 1) / TB, TB, 0, se>>>(ei);
    k_scan1 <<<N_SBLK, SCAN_B, 0, se>>>();
    k_scan3 <<<(N_NODES + TB - 1) / TB, TB, 0, se>>>();
    k_fill  <<<(N_EDGES + TB - 1) / TB, TB, 0, se>>>(ei);
    cudaEventRecord(evJoin, se);

    // branch B (default): transpose + raw GEMM layer 1
    k_transpose<<<tg, dim3(32, 8)>>>(X);
    k_gemm <<<gemm_blocks, TB>>>(0, W1);

    // join
    cudaStreamWaitEvent(0, evJoin, 0);

    // ---- layer 1 aggregation (applies dinv per edge) ----
    k_agg  <<<agg_blocks, 512>>>(0, b1, s1);

    // ---- layer 2 (pre-scaled path) ----
    k_gemm <<<gemm_blocks, TB>>>(1, W2);
    k_agg  <<<agg_blocks, 512>>>(1, b2, s2);

    // ---- GraphNorm + GELU ----
    k_final<<<4096, TB>>>(gnw, gnb, gnm, out);

    cudaEventDestroy(evFork);
    cudaEventDestroy(evJoin);
    cudaStreamDestroy(se);
}